// round 15
// baseline (speedup 1.0000x reference)
#include <cuda_runtime.h>
#include <cuda_fp16.h>
#include <math.h>
#include <stdint.h>

// Problem constants
#define NODESG   116
#define HEADS    2
#define DHEAD    116
#define HIDD     256
#define BGRAPH   512
#define NTOT     (BGRAPH * NODESG)      // 59392
#define DEG      8
#define DOUT     232
#define PSTRIDE  1024                   // padded fused output width (q|k|v|s|pad)
#define NPACK    928                    // valid columns (4*232)

// GEMM tiling
#define BM 128
#define BN 128
#define BK 32
#define RSH 40                           // smem row stride in halves (80 B, conflict-free)
#define RSB (RSH * 2)                    // 80 bytes
#define STG_B (BM * RSB)                 // bytes per operand per stage = 10240
#define NSTAGE 4
#define GEMM_SMEM (NSTAGE * 2 * STG_B)   // 81920 B

// fused attention kernel smem: K | V | HP sections, fp16
#define HSEC (NODESG * DOUT)             // 26912 halves per section
#define ATTN_SMEM (3 * HSEC * 2)         // 161472 B

// Scratch (device globals: no allocation allowed)
__device__ __half d_Ah[(size_t)NTOT * HIDD];                  // A fp16
__device__ __half d_Wh[PSTRIDE * HIDD];                       // W^T padded fp16
__device__ __half d_Ph[(size_t)NTOT * PSTRIDE];               // fused projections (fp16)
__device__ int   d_is32;                                      // edge_index dtype flag

// ---------------------------------------------------------------------------
// helpers
// ---------------------------------------------------------------------------
__device__ __forceinline__ void mma16816(float* c, const uint32_t* a, const uint32_t* b) {
    asm volatile(
        "mma.sync.aligned.m16n8k16.row.col.f32.f16.f16.f32 "
        "{%0,%1,%2,%3},{%4,%5,%6,%7},{%8,%9},{%0,%1,%2,%3};"
        : "+f"(c[0]), "+f"(c[1]), "+f"(c[2]), "+f"(c[3])
        : "r"(a[0]), "r"(a[1]), "r"(a[2]), "r"(a[3]), "r"(b[0]), "r"(b[1]));
}
__device__ __forceinline__ void ldsm_x4(uint32_t* r, uint32_t addr) {
    asm volatile("ldmatrix.sync.aligned.m8n8.x4.shared.b16 {%0,%1,%2,%3}, [%4];"
                 : "=r"(r[0]), "=r"(r[1]), "=r"(r[2]), "=r"(r[3]) : "r"(addr));
}
__device__ __forceinline__ uint32_t smem_u32(const void* p) {
    uint32_t a;
    asm("{ .reg .u64 t; cvta.to.shared.u64 t, %1; cvt.u32.u64 %0, t; }" : "=r"(a) : "l"(p));
    return a;
}
__device__ __forceinline__ void cp16(uint32_t dst, const void* src) {
    asm volatile("cp.async.cg.shared.global [%0], [%1], 16;" :: "r"(dst), "l"(src));
}
// unpack one uint4 (8 halves) into 8 floats
__device__ __forceinline__ void unpack8(float* f, uint4 u) {
    float2 a = __half22float2(*(__half2*)&u.x);
    float2 b = __half22float2(*(__half2*)&u.y);
    float2 c = __half22float2(*(__half2*)&u.z);
    float2 d = __half22float2(*(__half2*)&u.w);
    f[0] = a.x; f[1] = a.y; f[2] = b.x; f[3] = b.y;
    f[4] = c.x; f[5] = c.y; f[6] = d.x; f[7] = d.y;
}
// load 8 halves of a 232-half section; lanes >= 29 get zeros
__device__ __forceinline__ void ld8(float* f, const __half* p, int lane, bool v) {
    if (v) {
        unpack8(f, *(const uint4*)(p + lane * 8));
    } else {
#pragma unroll
        for (int j = 0; j < 8; j++) f[j] = 0.0f;
    }
}

// ---------------------------------------------------------------------------
// 0) edge_index dtype detection: int64 little-endian => all odd int32 words 0
// ---------------------------------------------------------------------------
__global__ void detect_kernel(const int* __restrict__ ei) {
    int j = blockIdx.x * blockDim.x + threadIdx.x;
    if (j < 4096) {
        if (ei[2 * j + 1] != 0) atomicOr(&d_is32, 1);
    }
}

// ---------------------------------------------------------------------------
// 1a) A prep: straight fp16 convert
// ---------------------------------------------------------------------------
__global__ __launch_bounds__(256) void aprep_kernel(const float* __restrict__ h) {
    int gi = blockIdx.x * blockDim.x + threadIdx.x;    // 8-float group index
    if (gi >= NTOT * HIDD / 8) return;
    const float4* src = (const float4*)(h + (size_t)gi * 8);
    float4 v0 = src[0], v1 = src[1];
    __half2 o[4];
    o[0] = __floats2half2_rn(v0.x, v0.y);
    o[1] = __floats2half2_rn(v0.z, v0.w);
    o[2] = __floats2half2_rn(v1.x, v1.y);
    o[3] = __floats2half2_rn(v1.z, v1.w);
    *(uint4*)(d_Ah + (size_t)gi * 8) = *(uint4*)o;
}

// ---------------------------------------------------------------------------
// 1b) pack W^T fp16: d_Wh[n][k], zero-padded n >= 928
// ---------------------------------------------------------------------------
__global__ __launch_bounds__(256) void pack_kernel(
        const float* __restrict__ Wq, const float* __restrict__ Wk,
        const float* __restrict__ Wv, const float* __restrict__ Ws) {
    int pi = blockIdx.x * blockDim.x + threadIdx.x;    // pair index
    if (pi >= PSTRIDE * HIDD / 2) return;
    int n = pi >> 7;
    int k = (pi & 127) * 2;
    float v0 = 0.0f, v1 = 0.0f;
    if      (n < 232) { v0 = Wq[k * 232 + n];       v1 = Wq[(k + 1) * 232 + n]; }
    else if (n < 464) { v0 = Wk[k * 232 + n - 232]; v1 = Wk[(k + 1) * 232 + n - 232]; }
    else if (n < 696) { v0 = Wv[k * 232 + n - 464]; v1 = Wv[(k + 1) * 232 + n - 464]; }
    else if (n < 928) { v0 = Ws[k * 232 + n - 696]; v1 = Ws[(k + 1) * 232 + n - 696]; }
    ((__half2*)d_Wh)[pi] = __floats2half2_rn(v0, v1);
}

// ---------------------------------------------------------------------------
// 2) fp16 mma.sync GEMM: P[N,1024] = h[N,256] @ W[256,1024], fp16 output
//    4-stage cp.async ring, prefetch 2, fragments via ldmatrix
// ---------------------------------------------------------------------------
__global__ __launch_bounds__(256, 2) void gemm_mma_kernel() {
    extern __shared__ __align__(16) char sm[];
    int tid  = threadIdx.x;
    int lane = tid & 31;
    int warp = tid >> 5;
    int wr = warp >> 2;          // 0..1 (M)
    int wc = warp & 3;           // 0..3 (N)
    int gid = lane >> 2;         // 0..7
    int tig = lane & 3;          // 0..3
    int brow = blockIdx.y * BM;
    int bcol = blockIdx.x * BN;

    const __half* Ag = d_Ah + (size_t)brow * HIDD;
    const __half* Bg = d_Wh + (size_t)bcol * HIDD;

    uint32_t sbase = smem_u32(sm);
    int rr0 = tid >> 2;          // 0..63 (+64 for second)
    int cc  = tid & 3;           // 16B unit within 64B row

    int a_row = wr * 64 + (lane & 7) + ((lane >> 3) & 1) * 8;
    int a_col = (lane >> 4) * 16;
    int b_row = wc * 32 + (lane & 7) + (lane >> 4) * 8;
    int b_col = ((lane >> 3) & 1) * 16;
    uint32_t a_off = (uint32_t)(a_row * RSB + a_col);
    uint32_t b_off = (uint32_t)(b_row * RSB + b_col) + STG_B;

    float c[4][4][4];
#pragma unroll
    for (int mt = 0; mt < 4; mt++)
#pragma unroll
        for (int nt = 0; nt < 4; nt++)
#pragma unroll
            for (int q = 0; q < 4; q++) c[mt][nt][q] = 0.0f;

    auto stage_in = [&](int ch) {
        uint32_t stg = sbase + (ch & (NSTAGE - 1)) * 2 * STG_B;
        int kc0 = ch * BK;
#pragma unroll
        for (int t = 0; t < 2; t++) {
            int rr = rr0 + t * 64;
            uint32_t soff = (uint32_t)(rr * RSB + cc * 16);
            cp16(stg + soff, Ag + (size_t)rr * HIDD + kc0 + cc * 8);
            cp16(stg + STG_B + soff, Bg + (size_t)rr * HIDD + kc0 + cc * 8);
        }
        asm volatile("cp.async.commit_group;");
    };

    stage_in(0);
    stage_in(1);

    const int NCH = HIDD / BK;   // 8
    for (int ch = 0; ch < NCH; ch++) {
        if (ch + 2 < NCH) {
            stage_in(ch + 2);
            asm volatile("cp.async.wait_group 2;");
        } else if (ch + 1 < NCH) {
            asm volatile("cp.async.wait_group 1;");
        } else {
            asm volatile("cp.async.wait_group 0;");
        }
        __syncthreads();

        uint32_t stg = sbase + (ch & (NSTAGE - 1)) * 2 * STG_B;

#pragma unroll
        for (int ks = 0; ks < 2; ks++) {
            uint32_t af[4][4];
#pragma unroll
            for (int mt = 0; mt < 4; mt++)
                ldsm_x4(af[mt], stg + a_off + mt * 16 * RSB + ks * 32);
            uint32_t bf[2][4];
#pragma unroll
            for (int p = 0; p < 2; p++)
                ldsm_x4(bf[p], stg + b_off + p * 16 * RSB + ks * 32);
#pragma unroll
            for (int mt = 0; mt < 4; mt++)
#pragma unroll
                for (int nt = 0; nt < 4; nt++)
                    mma16816(c[mt][nt], af[mt], &bf[nt >> 1][(nt & 1) * 2]);
        }
    }

    // Epilogue: packed fp16 stores to d_Ph, skip padded columns >= 928
#pragma unroll
    for (int mt = 0; mt < 4; mt++) {
        int r0 = brow + wr * 64 + mt * 16 + gid;
#pragma unroll
        for (int nt = 0; nt < 4; nt++) {
            int gc = bcol + wc * 32 + nt * 8 + tig * 2;
            if (gc < NPACK) {
                __half* p = d_Ph + (size_t)r0 * PSTRIDE + gc;
                *(__half2*)p = __floats2half2_rn(c[mt][nt][0], c[mt][nt][1]);
                *(__half2*)(p + 8 * PSTRIDE) = __floats2half2_rn(c[mt][nt][2], c[mt][nt][3]);
            }
        }
    }
}

// ---------------------------------------------------------------------------
// 3) fused attention + per-graph softmax + output. CTA = one graph, 512 thr.
//    Graph's K and V sections staged into smem (read once from DRAM);
//    per-edge gathers become conflict-free LDS. h_proj kept in smem fp16.
// ---------------------------------------------------------------------------
__global__ __launch_bounds__(512) void attn_finalize_kernel(
        const int* __restrict__ esrc, float* __restrict__ out) {
    extern __shared__ __align__(16) __half hsm[];   // K | V | HP (HSEC halves each)
    __shared__ float sh[128];
    __shared__ float e_sh[NODESG];
    __shared__ float alpha_sh[NODESG];

    int g = blockIdx.x;
    int tid = threadIdx.x;
    int w = tid >> 5, lane = tid & 31;
    int is32 = d_is32;
    bool vl = lane < 29;                            // 29 * 16B = 232 halves

    // ---- stage K and V sections into smem (cp.async) ----
    uint32_t sb = smem_u32(hsm);
    for (int idx = tid; idx < 2 * NODESG * 29; idx += 512) {
        int sec = (idx >= NODESG * 29) ? 1 : 0;
        int rem = idx - sec * NODESG * 29;
        int row = rem / 29;
        int ch  = rem - row * 29;
        const __half* src = d_Ph + (size_t)(g * NODESG + row) * PSTRIDE
                            + 232 + sec * 232 + ch * 8;
        cp16(sb + (uint32_t)((sec * HSEC + row * DOUT) * 2 + ch * 16), src);
    }
    asm volatile("cp.async.commit_group;");
    asm volatile("cp.async.wait_group 0;");
    __syncthreads();

    float sel[8];                                   // 1 = head0 (half index < 116)
#pragma unroll
    for (int j = 0; j < 8; j++) sel[j] = (lane * 8 + j < DHEAD) ? 1.0f : 0.0f;

    const float scale = 0.09284766908852593f;       // 1/sqrt(116)

    for (int n = w; n < NODESG; n += 16) {
        int i = g * NODESG + n;
        const __half* Prow = d_Ph + (size_t)i * PSTRIDE;

        float qf[8];
        ld8(qf, Prow, lane, vl);

        int myedge = 0;
        if (lane < DEG) {
            int e = i * DEG + lane;
            myedge = is32 ? esrc[e] : esrc[2 * e];  // int64: low word
        }
        int srcs[DEG];
#pragma unroll
        for (int e = 0; e < DEG; e++)
            srcs[e] = __shfl_sync(0xffffffffu, myedge, e) - g * NODESG;  // local

        float s0[DEG], s1[DEG];
#pragma unroll
        for (int e = 0; e < DEG; e++) {
            float kf[8];
            ld8(kf, hsm + srcs[e] * DOUT, lane, vl);
            float tot = 0.0f, a0 = 0.0f;
#pragma unroll
            for (int j = 0; j < 8; j++) {
                float p = qf[j] * kf[j];
                tot += p;
                a0 += sel[j] * p;
            }
#pragma unroll
            for (int off = 16; off > 0; off >>= 1) {
                tot += __shfl_xor_sync(0xffffffffu, tot, off);
                a0  += __shfl_xor_sync(0xffffffffu, a0, off);
            }
            s0[e] = a0 * scale;
            s1[e] = (tot - a0) * scale;
        }

        float m0 = s0[0], m1 = s1[0];
#pragma unroll
        for (int e = 1; e < DEG; e++) { m0 = fmaxf(m0, s0[e]); m1 = fmaxf(m1, s1[e]); }
        float ex0[DEG], ex1[DEG], den0 = 0.0f, den1 = 0.0f;
#pragma unroll
        for (int e = 0; e < DEG; e++) {
            ex0[e] = __expf(s0[e] - m0);
            ex1[e] = __expf(s1[e] - m1);
            den0 += ex0[e]; den1 += ex1[e];
        }
        float r0 = 1.0f / (den0 + 1e-16f);
        float r1 = 1.0f / (den1 + 1e-16f);

        float o[8];
#pragma unroll
        for (int j = 0; j < 8; j++) o[j] = 0.0f;
#pragma unroll
        for (int e = 0; e < DEG; e++) {
            float vf[8];
            ld8(vf, hsm + HSEC + srcs[e] * DOUT, lane, vl);
            float al0 = ex0[e] * r0, al1 = ex1[e] * r1;
            float d01 = al0 - al1;
#pragma unroll
            for (int j = 0; j < 8; j++) o[j] += (al1 + sel[j] * d01) * vf[j];
        }
        float sf[8];
        ld8(sf, Prow + 696, lane, vl);
#pragma unroll
        for (int j = 0; j < 8; j++) o[j] += sf[j];

        float psum = 0.0f;
#pragma unroll
        for (int j = 0; j < 8; j++) psum += o[j];
#pragma unroll
        for (int off = 16; off > 0; off >>= 1) psum += __shfl_xor_sync(0xffffffffu, psum, off);
        if (lane == 0) e_sh[n] = psum * (1.0f / (float)DOUT);

        if (vl) {
            __half2 oh[4];
            oh[0] = __floats2half2_rn(o[0], o[1]);
            oh[1] = __floats2half2_rn(o[2], o[3]);
            oh[2] = __floats2half2_rn(o[4], o[5]);
            oh[3] = __floats2half2_rn(o[6], o[7]);
            *(uint4*)(hsm + 2 * HSEC + n * DOUT + lane * 8) = *(uint4*)oh;
        }
    }
    __syncthreads();

    // per-graph softmax over e_sh[0..115]
    if (tid < 128) sh[tid] = (tid < NODESG) ? e_sh[tid] : -3.4e38f;
    __syncthreads();
#pragma unroll
    for (int s = 64; s > 0; s >>= 1) {
        if (tid < s) sh[tid] = fmaxf(sh[tid], sh[tid + s]);
        __syncthreads();
    }
    float m = sh[0];
    __syncthreads();
    float ex = (tid < NODESG) ? __expf(e_sh[tid] - m) : 0.0f;
    if (tid < 128) sh[tid] = ex;
    __syncthreads();
#pragma unroll
    for (int s = 64; s > 0; s >>= 1) {
        if (tid < s) sh[tid] += sh[tid + s];
        __syncthreads();
    }
    float inv = 1.0f / sh[0];
    if (tid < NODESG) {
        float a = ex * inv;
        out[g * NODESG + tid] = a;
        alpha_sh[tid] = a;
    }
    __syncthreads();

    // weighted output: 464 threads = 2 node-streams x 232 cols
    float* dst = out + NTOT + (size_t)g * (NODESG * DOUT);
    if (tid < 2 * DOUT) {
        int half = (tid >= DOUT) ? 1 : 0;
        int col = tid - half * DOUT;
        for (int n = half; n < NODESG; n += 2) {
            dst[n * DOUT + col] =
                alpha_sh[n] * __half2float(hsm[2 * HSEC + n * DOUT + col]);
        }
    }
}

// ---------------------------------------------------------------------------
extern "C" void kernel_launch(void* const* d_in, const int* in_sizes, int n_in,
                              void* d_out, int out_size) {
    const float* h  = (const float*)d_in[0];
    const int*   ei = (const int*)d_in[1];
    // d_in[2] = batch_index (unused: batch = i / 116 by construction)
    const float* Wq = (const float*)d_in[3];
    const float* Wk = (const float*)d_in[4];
    const float* Wv = (const float*)d_in[5];
    const float* Ws = (const float*)d_in[6];
    float* out = (float*)d_out;

    cudaFuncSetAttribute(gemm_mma_kernel,
                         cudaFuncAttributeMaxDynamicSharedMemorySize, GEMM_SMEM);
    cudaFuncSetAttribute(attn_finalize_kernel,
                         cudaFuncAttributeMaxDynamicSharedMemorySize, ATTN_SMEM);

    void* flag_ptr = nullptr;
    cudaGetSymbolAddress(&flag_ptr, d_is32);
    cudaMemsetAsync(flag_ptr, 0, sizeof(int));

    detect_kernel<<<16, 256>>>(ei);
    pack_kernel<<<(PSTRIDE * HIDD / 2 + 255) / 256, 256>>>(Wq, Wk, Wv, Ws);
    aprep_kernel<<<(NTOT * HIDD / 8 + 255) / 256, 256>>>(h);

    dim3 gg(PSTRIDE / BN, NTOT / BM);   // x=8 (ncol, fastest -> A reuse), y=464
    gemm_mma_kernel<<<gg, 256, GEMM_SMEM>>>();

    attn_finalize_kernel<<<BGRAPH, 512, ATTN_SMEM>>>(ei, out);
}

// round 17
// speedup vs baseline: 1.2190x; 1.2190x over previous
#include <cuda_runtime.h>
#include <cuda_fp16.h>
#include <math.h>
#include <stdint.h>

// Problem constants
#define NODESG   116
#define HEADS    2
#define DHEAD    116
#define HIDD     256
#define BGRAPH   512
#define NTOT     (BGRAPH * NODESG)      // 59392
#define DEG      8
#define DOUT     232
#define PSTRIDE  1024                   // padded fused output width (q|k|v|s|pad)
#define NPACK    928                    // valid columns (4*232)

// GEMM tiling
#define BM 128
#define BN 128
#define BK 32
#define RSH 40                           // smem row stride in halves (80 B, conflict-free)
#define RSB (RSH * 2)                    // 80 bytes
#define STG_B (BM * RSB)                 // bytes per operand per stage = 10240
#define NSTAGE 4
#define GEMM_SMEM (NSTAGE * 2 * STG_B)   // 81920 B
#define ATTN_SMEM (NODESG * DOUT * 2)    // 53824 B (fp16 h_proj scratch)

// Scratch (device globals: no allocation allowed)
__device__ __half d_Ah[(size_t)NTOT * HIDD];                  // A fp16
__device__ __half d_Wh[PSTRIDE * HIDD];                       // W^T padded fp16
__device__ __half d_Ph[(size_t)NTOT * PSTRIDE];               // fused projections (fp16)
__device__ int   d_is32;                                      // edge_index dtype flag

// ---------------------------------------------------------------------------
// helpers
// ---------------------------------------------------------------------------
__device__ __forceinline__ void mma16816(float* c, const uint32_t* a, const uint32_t* b) {
    asm volatile(
        "mma.sync.aligned.m16n8k16.row.col.f32.f16.f16.f32 "
        "{%0,%1,%2,%3},{%4,%5,%6,%7},{%8,%9},{%0,%1,%2,%3};"
        : "+f"(c[0]), "+f"(c[1]), "+f"(c[2]), "+f"(c[3])
        : "r"(a[0]), "r"(a[1]), "r"(a[2]), "r"(a[3]), "r"(b[0]), "r"(b[1]));
}
__device__ __forceinline__ void ldsm_x4(uint32_t* r, uint32_t addr) {
    asm volatile("ldmatrix.sync.aligned.m8n8.x4.shared.b16 {%0,%1,%2,%3}, [%4];"
                 : "=r"(r[0]), "=r"(r[1]), "=r"(r[2]), "=r"(r[3]) : "r"(addr));
}
__device__ __forceinline__ uint32_t smem_u32(const void* p) {
    uint32_t a;
    asm("{ .reg .u64 t; cvta.to.shared.u64 t, %1; cvt.u32.u64 %0, t; }" : "=r"(a) : "l"(p));
    return a;
}
__device__ __forceinline__ void cp16(uint32_t dst, const void* src) {
    asm volatile("cp.async.cg.shared.global [%0], [%1], 16;" :: "r"(dst), "l"(src));
}
// load 8 halves (one uint4) of a 232-half section; lanes >= 29 get zeros
__device__ __forceinline__ void ld8(float* f, const __half* p, int lane, bool v) {
    if (v) {
        uint4 u = *(const uint4*)(p + lane * 8);
        float2 a = __half22float2(*(__half2*)&u.x);
        float2 b = __half22float2(*(__half2*)&u.y);
        float2 c = __half22float2(*(__half2*)&u.z);
        float2 d = __half22float2(*(__half2*)&u.w);
        f[0] = a.x; f[1] = a.y; f[2] = b.x; f[3] = b.y;
        f[4] = c.x; f[5] = c.y; f[6] = d.x; f[7] = d.y;
    } else {
#pragma unroll
        for (int j = 0; j < 8; j++) f[j] = 0.0f;
    }
}

// ---------------------------------------------------------------------------
// 0) edge_index dtype detection: int64 little-endian => all odd int32 words 0
// ---------------------------------------------------------------------------
__global__ void detect_kernel(const int* __restrict__ ei) {
    int j = blockIdx.x * blockDim.x + threadIdx.x;
    if (j < 4096) {
        if (ei[2 * j + 1] != 0) atomicOr(&d_is32, 1);
    }
}

// ---------------------------------------------------------------------------
// 1a) A prep: straight fp16 convert
// ---------------------------------------------------------------------------
__global__ __launch_bounds__(256) void aprep_kernel(const float* __restrict__ h) {
    int gi = blockIdx.x * blockDim.x + threadIdx.x;    // 8-float group index
    if (gi >= NTOT * HIDD / 8) return;
    const float4* src = (const float4*)(h + (size_t)gi * 8);
    float4 v0 = src[0], v1 = src[1];
    __half2 o[4];
    o[0] = __floats2half2_rn(v0.x, v0.y);
    o[1] = __floats2half2_rn(v0.z, v0.w);
    o[2] = __floats2half2_rn(v1.x, v1.y);
    o[3] = __floats2half2_rn(v1.z, v1.w);
    *(uint4*)(d_Ah + (size_t)gi * 8) = *(uint4*)o;
}

// ---------------------------------------------------------------------------
// 1b) pack W^T fp16: d_Wh[n][k], zero-padded n >= 928
// ---------------------------------------------------------------------------
__global__ __launch_bounds__(256) void pack_kernel(
        const float* __restrict__ Wq, const float* __restrict__ Wk,
        const float* __restrict__ Wv, const float* __restrict__ Ws) {
    int pi = blockIdx.x * blockDim.x + threadIdx.x;    // pair index
    if (pi >= PSTRIDE * HIDD / 2) return;
    int n = pi >> 7;
    int k = (pi & 127) * 2;
    float v0 = 0.0f, v1 = 0.0f;
    if      (n < 232) { v0 = Wq[k * 232 + n];       v1 = Wq[(k + 1) * 232 + n]; }
    else if (n < 464) { v0 = Wk[k * 232 + n - 232]; v1 = Wk[(k + 1) * 232 + n - 232]; }
    else if (n < 696) { v0 = Wv[k * 232 + n - 464]; v1 = Wv[(k + 1) * 232 + n - 464]; }
    else if (n < 928) { v0 = Ws[k * 232 + n - 696]; v1 = Ws[(k + 1) * 232 + n - 696]; }
    ((__half2*)d_Wh)[pi] = __floats2half2_rn(v0, v1);
}

// ---------------------------------------------------------------------------
// 2) fp16 mma.sync GEMM: P[N,1024] = h[N,256] @ W[256,1024], fp16 output
//    4-stage cp.async ring, prefetch 2, fragments via ldmatrix
// ---------------------------------------------------------------------------
__global__ __launch_bounds__(256, 2) void gemm_mma_kernel() {
    extern __shared__ __align__(16) char sm[];
    int tid  = threadIdx.x;
    int lane = tid & 31;
    int warp = tid >> 5;
    int wr = warp >> 2;          // 0..1 (M)
    int wc = warp & 3;           // 0..3 (N)
    int gid = lane >> 2;         // 0..7
    int tig = lane & 3;          // 0..3
    int brow = blockIdx.y * BM;
    int bcol = blockIdx.x * BN;

    const __half* Ag = d_Ah + (size_t)brow * HIDD;
    const __half* Bg = d_Wh + (size_t)bcol * HIDD;

    uint32_t sbase = smem_u32(sm);
    int rr0 = tid >> 2;          // 0..63 (+64 for second)
    int cc  = tid & 3;           // 16B unit within 64B row

    int a_row = wr * 64 + (lane & 7) + ((lane >> 3) & 1) * 8;
    int a_col = (lane >> 4) * 16;
    int b_row = wc * 32 + (lane & 7) + (lane >> 4) * 8;
    int b_col = ((lane >> 3) & 1) * 16;
    uint32_t a_off = (uint32_t)(a_row * RSB + a_col);
    uint32_t b_off = (uint32_t)(b_row * RSB + b_col) + STG_B;

    float c[4][4][4];
#pragma unroll
    for (int mt = 0; mt < 4; mt++)
#pragma unroll
        for (int nt = 0; nt < 4; nt++)
#pragma unroll
            for (int q = 0; q < 4; q++) c[mt][nt][q] = 0.0f;

    auto stage_in = [&](int ch) {
        uint32_t stg = sbase + (ch & (NSTAGE - 1)) * 2 * STG_B;
        int kc0 = ch * BK;
#pragma unroll
        for (int t = 0; t < 2; t++) {
            int rr = rr0 + t * 64;
            uint32_t soff = (uint32_t)(rr * RSB + cc * 16);
            cp16(stg + soff, Ag + (size_t)rr * HIDD + kc0 + cc * 8);
            cp16(stg + STG_B + soff, Bg + (size_t)rr * HIDD + kc0 + cc * 8);
        }
        asm volatile("cp.async.commit_group;");
    };

    stage_in(0);
    stage_in(1);

    const int NCH = HIDD / BK;   // 8
    for (int ch = 0; ch < NCH; ch++) {
        if (ch + 2 < NCH) {
            stage_in(ch + 2);
            asm volatile("cp.async.wait_group 2;");
        } else if (ch + 1 < NCH) {
            asm volatile("cp.async.wait_group 1;");
        } else {
            asm volatile("cp.async.wait_group 0;");
        }
        __syncthreads();

        uint32_t stg = sbase + (ch & (NSTAGE - 1)) * 2 * STG_B;

#pragma unroll
        for (int ks = 0; ks < 2; ks++) {
            uint32_t af[4][4];
#pragma unroll
            for (int mt = 0; mt < 4; mt++)
                ldsm_x4(af[mt], stg + a_off + mt * 16 * RSB + ks * 32);
            uint32_t bf[2][4];
#pragma unroll
            for (int p = 0; p < 2; p++)
                ldsm_x4(bf[p], stg + b_off + p * 16 * RSB + ks * 32);
#pragma unroll
            for (int mt = 0; mt < 4; mt++)
#pragma unroll
                for (int nt = 0; nt < 4; nt++)
                    mma16816(c[mt][nt], af[mt], &bf[nt >> 1][(nt & 1) * 2]);
        }
    }

    // Epilogue: packed fp16 stores to d_Ph, skip padded columns >= 928
#pragma unroll
    for (int mt = 0; mt < 4; mt++) {
        int r0 = brow + wr * 64 + mt * 16 + gid;
#pragma unroll
        for (int nt = 0; nt < 4; nt++) {
            int gc = bcol + wc * 32 + nt * 8 + tig * 2;
            if (gc < NPACK) {
                __half* p = d_Ph + (size_t)r0 * PSTRIDE + gc;
                *(__half2*)p = __floats2half2_rn(c[mt][nt][0], c[mt][nt][1]);
                *(__half2*)(p + 8 * PSTRIDE) = __floats2half2_rn(c[mt][nt][2], c[mt][nt][3]);
            }
        }
    }
}

// ---------------------------------------------------------------------------
// 3) fused attention + per-graph softmax + output. CTA = one graph, 256 thr.
//    Gathers stay in global (L2-resident); h_proj scratch in smem fp16
//    (54 KB -> 4 CTAs/SM for latency hiding).
// ---------------------------------------------------------------------------
__global__ __launch_bounds__(256) void attn_finalize_kernel(
        const int* __restrict__ esrc, float* __restrict__ out) {
    extern __shared__ __align__(16) __half hp[];    // [116][232] fp16
    __shared__ float sh[128];
    __shared__ float e_sh[NODESG];
    __shared__ float alpha_sh[NODESG];

    int g = blockIdx.x;
    int tid = threadIdx.x;
    int w = tid >> 5, lane = tid & 31;
    int is32 = d_is32;
    bool vl = lane < 29;                            // 29 * 8 = 232 halves

    float sel[8];                                   // 1 = head0 (half index < 116)
#pragma unroll
    for (int j = 0; j < 8; j++) sel[j] = (lane * 8 + j < DHEAD) ? 1.0f : 0.0f;

    const float scale = 0.09284766908852593f;       // 1/sqrt(116)

    for (int n = w; n < NODESG; n += 8) {
        int i = g * NODESG + n;
        const __half* Prow = d_Ph + (size_t)i * PSTRIDE;

        float qf[8];
        ld8(qf, Prow, lane, vl);

        int myedge = 0;
        if (lane < DEG) {
            int e = i * DEG + lane;
            myedge = is32 ? esrc[e] : esrc[2 * e];  // int64: low word
        }
        int srcs[DEG];
#pragma unroll
        for (int e = 0; e < DEG; e++) srcs[e] = __shfl_sync(0xffffffffu, myedge, e);

        float s0[DEG], s1[DEG];
#pragma unroll
        for (int e = 0; e < DEG; e++) {
            float kf[8];
            ld8(kf, d_Ph + (size_t)srcs[e] * PSTRIDE + 232, lane, vl);
            float tot = 0.0f, a0 = 0.0f;
#pragma unroll
            for (int j = 0; j < 8; j++) {
                float p = qf[j] * kf[j];
                tot += p;
                a0 += sel[j] * p;
            }
#pragma unroll
            for (int off = 16; off > 0; off >>= 1) {
                tot += __shfl_xor_sync(0xffffffffu, tot, off);
                a0  += __shfl_xor_sync(0xffffffffu, a0, off);
            }
            s0[e] = a0 * scale;
            s1[e] = (tot - a0) * scale;
        }

        float m0 = s0[0], m1 = s1[0];
#pragma unroll
        for (int e = 1; e < DEG; e++) { m0 = fmaxf(m0, s0[e]); m1 = fmaxf(m1, s1[e]); }
        float ex0[DEG], ex1[DEG], den0 = 0.0f, den1 = 0.0f;
#pragma unroll
        for (int e = 0; e < DEG; e++) {
            ex0[e] = __expf(s0[e] - m0);
            ex1[e] = __expf(s1[e] - m1);
            den0 += ex0[e]; den1 += ex1[e];
        }
        float r0 = 1.0f / (den0 + 1e-16f);
        float r1 = 1.0f / (den1 + 1e-16f);

        float o[8];
#pragma unroll
        for (int j = 0; j < 8; j++) o[j] = 0.0f;
#pragma unroll
        for (int e = 0; e < DEG; e++) {
            float vf[8];
            ld8(vf, d_Ph + (size_t)srcs[e] * PSTRIDE + 464, lane, vl);
            float al0 = ex0[e] * r0, al1 = ex1[e] * r1;
            float d01 = al0 - al1;
#pragma unroll
            for (int j = 0; j < 8; j++) o[j] += (al1 + sel[j] * d01) * vf[j];
        }
        float sf[8];
        ld8(sf, Prow + 696, lane, vl);
#pragma unroll
        for (int j = 0; j < 8; j++) o[j] += sf[j];

        float psum = 0.0f;
#pragma unroll
        for (int j = 0; j < 8; j++) psum += o[j];
#pragma unroll
        for (int off = 16; off > 0; off >>= 1) psum += __shfl_xor_sync(0xffffffffu, psum, off);
        if (lane == 0) e_sh[n] = psum * (1.0f / (float)DOUT);

        if (vl) {
            __half2 oh[4];
            oh[0] = __floats2half2_rn(o[0], o[1]);
            oh[1] = __floats2half2_rn(o[2], o[3]);
            oh[2] = __floats2half2_rn(o[4], o[5]);
            oh[3] = __floats2half2_rn(o[6], o[7]);
            *(uint4*)(hp + n * DOUT + lane * 8) = *(uint4*)oh;
        }
    }
    __syncthreads();

    // per-graph softmax over e_sh[0..115]
    if (tid < 128) sh[tid] = (tid < NODESG) ? e_sh[tid] : -3.4e38f;
    __syncthreads();
#pragma unroll
    for (int s = 64; s > 0; s >>= 1) {
        if (tid < s) sh[tid] = fmaxf(sh[tid], sh[tid + s]);
        __syncthreads();
    }
    float m = sh[0];
    __syncthreads();
    float ex = (tid < NODESG) ? __expf(e_sh[tid] - m) : 0.0f;
    if (tid < 128) sh[tid] = ex;
    __syncthreads();
#pragma unroll
    for (int s = 64; s > 0; s >>= 1) {
        if (tid < s) sh[tid] += sh[tid + s];
        __syncthreads();
    }
    float inv = 1.0f / sh[0];
    if (tid < NODESG) {
        float a = ex * inv;
        out[g * NODESG + tid] = a;
        alpha_sh[tid] = a;
    }
    __syncthreads();

    // weighted output
    float* dst = out + NTOT + (size_t)g * (NODESG * DOUT);
    if (tid < DOUT) {
#pragma unroll 4
        for (int n = 0; n < NODESG; n++) {
            dst[n * DOUT + tid] = alpha_sh[n] * __half2float(hp[n * DOUT + tid]);
        }
    }
}

// ---------------------------------------------------------------------------
extern "C" void kernel_launch(void* const* d_in, const int* in_sizes, int n_in,
                              void* d_out, int out_size) {
    const float* h  = (const float*)d_in[0];
    const int*   ei = (const int*)d_in[1];
    // d_in[2] = batch_index (unused: batch = i / 116 by construction)
    const float* Wq = (const float*)d_in[3];
    const float* Wk = (const float*)d_in[4];
    const float* Wv = (const float*)d_in[5];
    const float* Ws = (const float*)d_in[6];
    float* out = (float*)d_out;

    cudaFuncSetAttribute(gemm_mma_kernel,
                         cudaFuncAttributeMaxDynamicSharedMemorySize, GEMM_SMEM);
    cudaFuncSetAttribute(attn_finalize_kernel,
                         cudaFuncAttributeMaxDynamicSharedMemorySize, ATTN_SMEM);

    void* flag_ptr = nullptr;
    cudaGetSymbolAddress(&flag_ptr, d_is32);
    cudaMemsetAsync(flag_ptr, 0, sizeof(int));

    detect_kernel<<<16, 256>>>(ei);
    pack_kernel<<<(PSTRIDE * HIDD / 2 + 255) / 256, 256>>>(Wq, Wk, Wv, Ws);
    aprep_kernel<<<(NTOT * HIDD / 8 + 255) / 256, 256>>>(h);

    dim3 gg(PSTRIDE / BN, NTOT / BM);   // x=8 (ncol, fastest -> A reuse), y=464
    gemm_mma_kernel<<<gg, 256, GEMM_SMEM>>>();

    attn_finalize_kernel<<<BGRAPH, 256, ATTN_SMEM>>>(ei, out);
}